// round 14
// baseline (speedup 1.0000x reference)
#include <cuda_runtime.h>
#include <cuda_fp16.h>
#include <math.h>
#include <stdint.h>

// ---------------------------------------------------------------------------
// Problem constants
// ---------------------------------------------------------------------------
constexpr int Bc   = 512;
constexpr int Gc   = 131;
constexpr int MTOT = Bc * Gc;      // 67072
constexpr int LEAF_LO = 80;
constexpr int LEAF_HI = 130;

// Scratch (device globals: allocation-free)
__device__ __half g_q16[(size_t)MTOT * 512];    // q  (fp16)
__device__ __half g_h16[(size_t)MTOT * 512];    // h  (fp16)
__device__ __half g_Qp [(size_t)MTOT * 512];    // q' = q·M
__device__ __half g_X16[(size_t)MTOT * 512];    // X  = attn·h
__device__ __half g_W16[4][512 * 512];          // WqT, WkT, WvT, Wo (fp16)
__device__ __half g_WM16[2][512 * 512];         // Wm, Wn (folded, fp16)

// ---------------------------------------------------------------------------
// PTX helpers (baseline sm_75/80 PTX — valid for compute_103)
// ---------------------------------------------------------------------------
__device__ __forceinline__ uint32_t smem_u32(const void* p) {
    return (uint32_t)__cvta_generic_to_shared(p);
}
__device__ __forceinline__ void cp_async16(uint32_t sdst, const void* gsrc) {
    asm volatile("cp.async.cg.shared.global [%0], [%1], 16;" :: "r"(sdst), "l"(gsrc));
}
__device__ __forceinline__ void cp_async16z(uint32_t sdst, const void* gsrc, bool valid) {
    int sz = valid ? 16 : 0;
    asm volatile("cp.async.cg.shared.global [%0], [%1], 16, %2;"
                 :: "r"(sdst), "l"(gsrc), "r"(sz));
}
__device__ __forceinline__ void cp_commit() { asm volatile("cp.async.commit_group;"); }
__device__ __forceinline__ void cp_wait0()  { asm volatile("cp.async.wait_group 0;"); }
__device__ __forceinline__ void cp_wait1()  { asm volatile("cp.async.wait_group 1;"); }

__device__ __forceinline__ void ldsm_x4(uint32_t& r0, uint32_t& r1, uint32_t& r2,
                                        uint32_t& r3, uint32_t addr) {
    asm volatile("ldmatrix.sync.aligned.m8n8.x4.shared.b16 {%0,%1,%2,%3}, [%4];"
                 : "=r"(r0), "=r"(r1), "=r"(r2), "=r"(r3) : "r"(addr));
}
__device__ __forceinline__ void ldsm_x4_t(uint32_t& r0, uint32_t& r1, uint32_t& r2,
                                          uint32_t& r3, uint32_t addr) {
    asm volatile("ldmatrix.sync.aligned.m8n8.x4.trans.shared.b16 {%0,%1,%2,%3}, [%4];"
                 : "=r"(r0), "=r"(r1), "=r"(r2), "=r"(r3) : "r"(addr));
}
__device__ __forceinline__ void mma_f16(float* c, const uint32_t* a, const uint32_t* b) {
    asm volatile(
        "mma.sync.aligned.m16n8k16.row.col.f32.f16.f16.f32 "
        "{%0,%1,%2,%3}, {%4,%5,%6,%7}, {%8,%9}, {%0,%1,%2,%3};"
        : "+f"(c[0]), "+f"(c[1]), "+f"(c[2]), "+f"(c[3])
        : "r"(a[0]), "r"(a[1]), "r"(a[2]), "r"(a[3]), "r"(b[0]), "r"(b[1]));
}

// ---------------------------------------------------------------------------
// cvt h -> fp16 (runs on side stream, overlaps tiny2 + qM)
// ---------------------------------------------------------------------------
__global__ void cvt_h_kernel(const float4* __restrict__ in,
                             uint4* __restrict__ out, int n8) {
    int i = blockIdx.x * blockDim.x + threadIdx.x;
    int stride = gridDim.x * blockDim.x;
    for (; i < n8; i += stride) {
        float4 v0 = in[2 * i], v1 = in[2 * i + 1];
        __half2 h0 = __floats2half2_rn(v0.x, v0.y);
        __half2 h1 = __floats2half2_rn(v0.z, v0.w);
        __half2 h2 = __floats2half2_rn(v1.x, v1.y);
        __half2 h3 = __floats2half2_rn(v1.z, v1.w);
        uint4 o;
        o.x = *reinterpret_cast<uint32_t*>(&h0);
        o.y = *reinterpret_cast<uint32_t*>(&h1);
        o.z = *reinterpret_cast<uint32_t*>(&h2);
        o.w = *reinterpret_cast<uint32_t*>(&h3);
        out[i] = o;
    }
}

// prep_qw: z=0 cvt q->fp16, z=1..3 transpose+cvt Wq/Wk/Wv, z=4 plain cvt Wo.
__global__ void prep_qw_kernel(const float4* __restrict__ q, uint4* __restrict__ q16,
                               const float* __restrict__ w0, const float* __restrict__ w1,
                               const float* __restrict__ w2, const float* __restrict__ w3,
                               __half* __restrict__ wout, int n8) {
    const int tx = threadIdx.x, ty = threadIdx.y;
    const int tid = ty * 32 + tx;
    const int z = blockIdx.z;
    if (z == 0) {
        int blk = blockIdx.y * 16 + blockIdx.x;
        for (int i = blk * 256 + tid; i < n8; i += 256 * 256) {
            float4 v0 = q[2 * i], v1 = q[2 * i + 1];
            __half2 h0 = __floats2half2_rn(v0.x, v0.y);
            __half2 h1 = __floats2half2_rn(v0.z, v0.w);
            __half2 h2 = __floats2half2_rn(v1.x, v1.y);
            __half2 h3 = __floats2half2_rn(v1.z, v1.w);
            uint4 o;
            o.x = *reinterpret_cast<uint32_t*>(&h0);
            o.y = *reinterpret_cast<uint32_t*>(&h1);
            o.z = *reinterpret_cast<uint32_t*>(&h2);
            o.w = *reinterpret_cast<uint32_t*>(&h3);
            q16[i] = o;
        }
    } else {
        __shared__ float tile[32][33];
        const int sel = z - 1;
        const float* in = (sel == 0) ? w0 : (sel == 1) ? w1 : (sel == 2) ? w2 : w3;
        __half* o = wout + (size_t)sel * 512 * 512;
        const int x = blockIdx.x * 32 + tx;
        const int y0 = blockIdx.y * 32;
        if (sel < 3) {
#pragma unroll
            for (int j = 0; j < 32; j += 8)
                tile[ty + j][tx] = in[(size_t)(y0 + ty + j) * 512 + x];
            __syncthreads();
            const int x2 = y0 + tx;
            const int y2 = blockIdx.x * 32;
#pragma unroll
            for (int j = 0; j < 32; j += 8)
                o[(size_t)(y2 + ty + j) * 512 + x2] = __float2half_rn(tile[tx][ty + j]);
        } else {
#pragma unroll
            for (int j = 0; j < 32; j += 8)
                o[(size_t)(y0 + ty + j) * 512 + x] =
                    __float2half_rn(in[(size_t)(y0 + ty + j) * 512 + x]);
        }
    }
}

// ---------------------------------------------------------------------------
// fp16 mma GEMM-NT, 512 threads (16 warps, 4m x 4n, warp tile 32x32):
// C[M,N] = A[M,512] @ W[N,512]^T. BM=BN=128, BK=64, 3-stage pipeline.
// ---------------------------------------------------------------------------
constexpr int GM_ROWH = 72;
constexpr int GM_STAGE_B = 256 * GM_ROWH * 2;     // 36864
constexpr int GM_STAGES = 3;
constexpr int GM_SMEM = GM_STAGES * GM_STAGE_B;   // 110592
constexpr int GM_ITERS = 8;

template <bool OUTF32>
__device__ __forceinline__ void gemm_body_f16(const __half* __restrict__ A,
                                              const __half* __restrict__ W,
                                              const float* __restrict__ bias,
                                              void* __restrict__ Cv, int CS,
                                              int bm, int bn) {
    extern __shared__ __align__(16) char smraw[];
    const uint32_t smb = smem_u32(smraw);
    const int tid = threadIdx.x;
    const int wid = tid >> 5;
    const int lane = tid & 31;
    const int wm = (wid & 3) * 32;
    const int wn = (wid >> 2) * 32;

    const __half* Ag = A + (size_t)bm * 512;
    const __half* Wg = W + (size_t)bn * 512;

    float c[2][4][4];
#pragma unroll
    for (int t = 0; t < 2; t++)
#pragma unroll
        for (int n = 0; n < 4; n++)
#pragma unroll
            for (int v = 0; v < 4; v++) c[t][n][v] = 0.f;

    const int lr = lane & 7;
    uint32_t aoff[2], boff[2];
#pragma unroll
    for (int t = 0; t < 2; t++)
        aoff[t] = (uint32_t)(((wm + t * 16 + ((lane >> 3) & 1) * 8 + lr) * GM_ROWH
                              + (lane >> 4) * 8) * 2);
#pragma unroll
    for (int jp = 0; jp < 2; jp++)
        boff[jp] = (uint32_t)(128 * GM_ROWH * 2
                              + ((wn + jp * 16 + ((lane >> 4) & 1) * 8 + lr) * GM_ROWH
                                 + ((lane >> 3) & 1) * 8) * 2);

    auto load_stage = [&](int s, int k0) {
        uint32_t base = smb + (uint32_t)(s * GM_STAGE_B);
#pragma unroll
        for (int i = 0; i < 2; i++) {
            int id = tid + i * 512;
            int row = id >> 3, c8 = (id & 7) << 3;
            cp_async16(base + (uint32_t)((row * GM_ROWH + c8) * 2),
                       Ag + (size_t)row * 512 + k0 + c8);
        }
#pragma unroll
        for (int i = 0; i < 2; i++) {
            int id = tid + i * 512;
            int row = id >> 3, c8 = (id & 7) << 3;
            cp_async16(base + (uint32_t)(((128 + row) * GM_ROWH + c8) * 2),
                       Wg + (size_t)row * 512 + k0 + c8);
        }
    };

    load_stage(0, 0);    cp_commit();
    load_stage(1, 64);   cp_commit();
    cp_wait1();
    __syncthreads();

    int sc = 0, sl = 2;
    for (int it = 0; it < GM_ITERS; ++it) {
        if (it + 2 < GM_ITERS) {
            load_stage(sl, (it + 2) * 64);
            cp_commit();
            sl = (sl == GM_STAGES - 1) ? 0 : sl + 1;
        }
        uint32_t base = smb + (uint32_t)(sc * GM_STAGE_B);
        sc = (sc == GM_STAGES - 1) ? 0 : sc + 1;
#pragma unroll
        for (int kk = 0; kk < 4; kk++) {
            uint32_t a[2][4], b[4][2];
#pragma unroll
            for (int t = 0; t < 2; t++)
                ldsm_x4(a[t][0], a[t][1], a[t][2], a[t][3], base + aoff[t] + kk * 32);
#pragma unroll
            for (int jp = 0; jp < 2; jp++) {
                uint32_t r0, r1, r2, r3;
                ldsm_x4(r0, r1, r2, r3, base + boff[jp] + kk * 32);
                b[2 * jp][0] = r0;     b[2 * jp][1] = r1;
                b[2 * jp + 1][0] = r2; b[2 * jp + 1][1] = r3;
            }
#pragma unroll
            for (int t = 0; t < 2; t++)
#pragma unroll
                for (int n = 0; n < 4; n++)
                    mma_f16(c[t][n], a[t], b[n]);
        }
        if (it + 2 < GM_ITERS)      cp_wait1();
        else if (it + 1 < GM_ITERS) cp_wait0();
        __syncthreads();
    }

    const int g = lane >> 2;
    const int q = lane & 3;
#pragma unroll
    for (int n = 0; n < 4; n++) {
        int col = bn + wn + n * 8 + 2 * q;
        float b0 = 0.f, b1 = 0.f;
        if (OUTF32) { b0 = bias[col]; b1 = bias[col + 1]; }
#pragma unroll
        for (int t = 0; t < 2; t++) {
            int row0 = bm + wm + t * 16 + g;
            if (OUTF32) {
                float* Cf = (float*)Cv;
                *reinterpret_cast<float2*>(Cf + (size_t)row0 * CS + col) =
                    make_float2(c[t][n][0] + b0, c[t][n][1] + b1);
                *reinterpret_cast<float2*>(Cf + (size_t)(row0 + 8) * CS + col) =
                    make_float2(c[t][n][2] + b0, c[t][n][3] + b1);
            } else {
                __half* Ch = (__half*)Cv;
                __half2 p0 = __floats2half2_rn(c[t][n][0], c[t][n][1]);
                __half2 p1 = __floats2half2_rn(c[t][n][2], c[t][n][3]);
                *reinterpret_cast<__half2*>(Ch + (size_t)row0 * CS + col) = p0;
                *reinterpret_cast<__half2*>(Ch + (size_t)(row0 + 8) * CS + col) = p1;
            }
        }
    }
}

template <bool OUTF32>
__global__ void __launch_bounds__(512, 2)
mma_gemm_f16(const __half* __restrict__ A, const __half* __restrict__ W,
             const float* __restrict__ bias, void* __restrict__ C, int CS) {
    gemm_body_f16<OUTF32>(A, W, bias, C, CS, blockIdx.y * 128, blockIdx.x * 128);
}

__global__ void __launch_bounds__(512, 2)
tiny2_gemm_f16(const __half* __restrict__ A0, const __half* __restrict__ W0,
               __half* __restrict__ C0,
               const __half* __restrict__ A1, const __half* __restrict__ W1,
               __half* __restrict__ C1) {
    if (blockIdx.z == 0)
        gemm_body_f16<false>(A0, W0, nullptr, C0, 512, blockIdx.y * 128, blockIdx.x * 128);
    else
        gemm_body_f16<false>(A1, W1, nullptr, C1, 512, blockIdx.y * 128, blockIdx.x * 128);
}

// ---------------------------------------------------------------------------
// FUSED attention with direct softmax. grid (3, Bc):
//   x<2 -> 64-row mma tile; x==2 -> tail rows 128..130.
// Smem (dynamic, 97792 B):
//   region A [0, 78336): phase1 2x33408 scores pipeline -> phase3 2x39168 V
//   Ps at [78336, +19456): fp16 probs [64][152]
// Static: mask_s + row-stat exchange buffers.
// ---------------------------------------------------------------------------
constexpr int SC_QB   = 64 * 72 * 2;              // 9216
constexpr int SC_STG  = SC_QB + 168 * 72 * 2;     // 33408
constexpr int HV_TILE = 144 * 136 * 2;            // 39168 whole V n-tile
constexpr int PS_OFF  = 2 * HV_TILE;              // 78336
constexpr int PS_STR  = 152;
constexpr int AT_DYN  = PS_OFF + 64 * PS_STR * 2; // 97792

__global__ void __launch_bounds__(256)
attention_kernel(const __half* __restrict__ Q, const __half* __restrict__ Hm,
                 const int* __restrict__ mask, __half* __restrict__ X) {
    extern __shared__ __align__(16) char smc[];
    __shared__ int mask_s[144];
    __shared__ float s_max[64][4];
    __shared__ float s_sum[64][4];
    const uint32_t smb = smem_u32(smc);
    const int tid = threadIdx.x;
    const int wid = tid >> 5;
    const int lane = tid & 31;
    const int b = blockIdx.y;

    // ======================= TAIL CTA (rows 128..130) =======================
    if (blockIdx.x == 2) {
        float* qs = reinterpret_cast<float*>(smc);           // [3][512]
        float* ps = reinterpret_cast<float*>(smc + 6144);    // [3][132]
        int*   mk = reinterpret_cast<int*>(smc + 7808);      // [132]
        const __half* Qb = Q  + ((size_t)b * Gc + 128) * 512;
        const __half* hb = Hm + (size_t)b * Gc * 512;

        for (int i = tid; i < 3 * 512; i += 256) qs[i] = __half2float(Qb[i]);
        if (tid < 132) mk[tid] = (tid < Gc) ? mask[b * Gc + tid] : 1;
        __syncthreads();

        for (int j = wid; j < Gc; j += 8) {
            const __half* hj = hb + (size_t)j * 512;
            float a0 = 0.f, a1 = 0.f, a2 = 0.f;
#pragma unroll
            for (int k = 0; k < 16; k++) {
                int idx = lane + k * 32;
                float hv = __half2float(hj[idx]);
                a0 = fmaf(hv, qs[idx], a0);
                a1 = fmaf(hv, qs[512 + idx], a1);
                a2 = fmaf(hv, qs[1024 + idx], a2);
            }
#pragma unroll
            for (int o = 16; o; o >>= 1) {
                a0 += __shfl_xor_sync(0xffffffffu, a0, o);
                a1 += __shfl_xor_sync(0xffffffffu, a1, o);
                a2 += __shfl_xor_sync(0xffffffffu, a2, o);
            }
            if (lane == 0) { ps[j] = a0; ps[132 + j] = a1; ps[264 + j] = a2; }
        }
        __syncthreads();

        if (wid < 3) {
            const int gi = 128 + wid;
            const bool li = (gi >= LEAF_LO) && (gi < LEAF_HI);
            const float norm = 0.04419417382415922f;
            float v[5];
            float mx = -3.0e38f;
#pragma unroll
            for (int ch = 0; ch < 5; ch++) {
                int j = lane + ch * 32;
                float val = -3.0e38f;
                if (j < Gc) {
                    bool mj = (mk[j] > 0) || (li && j >= LEAF_LO && j < LEAF_HI);
                    val = mj ? -30.f : ps[wid * 132 + j] * norm;
                }
                v[ch] = val;
                mx = fmaxf(mx, val);
            }
#pragma unroll
            for (int o = 16; o; o >>= 1) mx = fmaxf(mx, __shfl_xor_sync(0xffffffffu, mx, o));
            float e[5];
            float sum = 0.f;
#pragma unroll
            for (int ch = 0; ch < 5; ch++) {
                int j = lane + ch * 32;
                e[ch] = (j < Gc) ? expf(v[ch] - mx) : 0.f;
                sum += e[ch];
            }
#pragma unroll
            for (int o = 16; o; o >>= 1) sum += __shfl_xor_sync(0xffffffffu, sum, o);
            float inv = 1.f / sum;
#pragma unroll
            for (int ch = 0; ch < 5; ch++) {
                int j = lane + ch * 32;
                if (j < Gc) {
                    bool mj = (mk[j] > 0) || (li && j >= LEAF_LO && j < LEAF_HI);
                    ps[wid * 132 + j] = mj ? 0.f : e[ch] * inv;
                }
            }
        }
        __syncthreads();

        float acc[3][2] = {{0.f, 0.f}, {0.f, 0.f}, {0.f, 0.f}};
        for (int j = 0; j < Gc; j++) {
            float p0 = ps[j], p1 = ps[132 + j], p2 = ps[264 + j];
            float h0 = __half2float(hb[(size_t)j * 512 + tid]);
            float h1 = __half2float(hb[(size_t)j * 512 + tid + 256]);
            acc[0][0] = fmaf(p0, h0, acc[0][0]); acc[0][1] = fmaf(p0, h1, acc[0][1]);
            acc[1][0] = fmaf(p1, h0, acc[1][0]); acc[1][1] = fmaf(p1, h1, acc[1][1]);
            acc[2][0] = fmaf(p2, h0, acc[2][0]); acc[2][1] = fmaf(p2, h1, acc[2][1]);
        }
        __half* Xb = X + ((size_t)b * Gc + 128) * 512;
#pragma unroll
        for (int i = 0; i < 3; i++) {
            Xb[(size_t)i * 512 + tid]       = __float2half_rn(acc[i][0]);
            Xb[(size_t)i * 512 + tid + 256] = __float2half_rn(acc[i][1]);
        }
        return;
    }

    // ======================= MAIN CTA (64 rows) =============================
    const int m0 = blockIdx.x * 64;
    if (tid < 144) mask_s[tid] = (tid < Gc) ? mask[b * Gc + tid] : 1;

    const __half* Qb = Q  + (size_t)b * Gc * 512;
    const __half* Kb = Hm + (size_t)b * Gc * 512;   // K and V are both h

    // whole-tile V loader (region A), usable after phase-1 final sync
    auto vload_tile = [&](int s, int n0) {
        uint32_t vbse = smb + (uint32_t)(s * HV_TILE);
#pragma unroll
        for (int i = 0; i < 9; i++) {
            int id = tid + i * 256;
            int row = id >> 4, c8 = (id & 15) << 3;
            bool v = row < Gc;
            const __half* src = v ? Kb + (size_t)row * 512 + n0 + c8 : Kb;
            cp_async16z(vbse + (uint32_t)((row * 136 + c8) * 2), src, v);
        }
    };

    // ---- phase 1: scores (fp16 mma), 2-stage pipeline, K=512 = 8 x 64 ----
    const int wm = (wid & 1) * 32;
    const int wn = (wid >> 1) * 40;
    const int lr = lane & 7;
    const int g  = lane >> 2;
    const int qd = lane & 3;

    float c[2][5][4];
#pragma unroll
    for (int t = 0; t < 2; t++)
#pragma unroll
        for (int n = 0; n < 5; n++)
#pragma unroll
            for (int v = 0; v < 4; v++) c[t][n][v] = 0.f;

    {
        uint32_t aoff[2], boff[3];
#pragma unroll
        for (int t = 0; t < 2; t++)
            aoff[t] = (uint32_t)(((wm + t * 16 + ((lane >> 3) & 1) * 8 + lr) * 72
                                  + (lane >> 4) * 8) * 2);
#pragma unroll
        for (int jp = 0; jp < 3; jp++)
            boff[jp] = (uint32_t)(SC_QB
                                  + ((wn + jp * 16 + ((lane >> 4) & 1) * 8 + lr) * 72
                                     + ((lane >> 3) & 1) * 8) * 2);

        auto load_stage = [&](int s, int k0) {
            uint32_t qb = smb + (uint32_t)(s * SC_STG);
            uint32_t kb = qb + SC_QB;
#pragma unroll
            for (int l = 0; l < 2; l++) {
                int id = tid + l * 256;
                int row = id >> 3, c8 = (id & 7) << 3;
                cp_async16(qb + (uint32_t)((row * 72 + c8) * 2),
                           Qb + (size_t)(m0 + row) * 512 + k0 + c8);
            }
#pragma unroll
            for (int i = 0; i < 5; i++) {
                int id = tid + i * 256;
                int row = id >> 3, c8 = (id & 7) << 3;
                bool v = row < Gc;
                const __half* src = v ? Kb + (size_t)row * 512 + k0 + c8 : Kb;
                cp_async16z(kb + (uint32_t)((row * 72 + c8) * 2), src, v);
            }
        };

        load_stage(0, 0);
        cp_commit();
        cp_wait0();
        __syncthreads();

        for (int it = 0; it < 8; ++it) {
            if (it + 1 < 8) {
                load_stage((it + 1) & 1, (it + 1) * 64);
                cp_commit();
            }
            uint32_t qb = smb + (uint32_t)((it & 1) * SC_STG);
#pragma unroll
            for (int kk = 0; kk < 4; kk++) {
                uint32_t a[2][4], bfr[6][2];
#pragma unroll
                for (int t = 0; t < 2; t++)
                    ldsm_x4(a[t][0], a[t][1], a[t][2], a[t][3], qb + aoff[t] + kk * 32);
#pragma unroll
                for (int jp = 0; jp < 3; jp++) {
                    uint32_t r0, r1, r2, r3;
                    ldsm_x4(r0, r1, r2, r3, qb + boff[jp] + kk * 32);
                    bfr[2 * jp][0] = r0;     bfr[2 * jp][1] = r1;
                    bfr[2 * jp + 1][0] = r2; bfr[2 * jp + 1][1] = r3;
                }
#pragma unroll
                for (int t = 0; t < 2; t++)
#pragma unroll
                    for (int n = 0; n < 5; n++)
                        mma_f16(c[t][n], a[t], bfr[n]);
            }
            if (it + 1 < 8) cp_wait0();
            __syncthreads();
        }
    }
    // region A free now: kick off V tile 0 so it loads during softmax
    vload_tile(0, 0);
    cp_commit();

    // ---- phase 2: direct softmax from accumulators -> Ps[64][152] fp16 ----
    {
        const int nw = wid >> 1;                    // n-warp index 0..3
        const float norm = 0.04419417382415922f;

        // mask + scale in place; per-row local maxima
        float mx[2][2] = {{-3.0e38f, -3.0e38f}, {-3.0e38f, -3.0e38f}};
#pragma unroll
        for (int t = 0; t < 2; t++)
#pragma unroll
            for (int n = 0; n < 5; n++)
#pragma unroll
                for (int v = 0; v < 4; v++) {
                    int row = m0 + wm + t * 16 + g + (v >> 1) * 8;
                    int col = wn + n * 8 + 2 * qd + (v & 1);
                    float val = -3.0e38f;
                    if (col < Gc) {
                        bool li = (row >= LEAF_LO) && (row < LEAF_HI);
                        bool mj = (mask_s[col] > 0) ||
                                  (li && col >= LEAF_LO && col < LEAF_HI);
                        val = mj ? -30.f : c[t][n][v] * norm;
                    }
                    c[t][n][v] = val;
                    mx[t][v >> 1] = fmaxf(mx[t][v >> 1], val);
                }
#pragma unroll
        for (int t = 0; t < 2; t++)
#pragma unroll
            for (int hh = 0; hh < 2; hh++) {
                float m = mx[t][hh];
                m = fmaxf(m, __shfl_xor_sync(0xffffffffu, m, 1));
                m = fmaxf(m, __shfl_xor_sync(0xffffffffu, m, 2));
                mx[t][hh] = m;
            }
        if (qd == 0) {
#pragma unroll
            for (int t = 0; t < 2; t++)
#pragma unroll
                for (int hh = 0; hh < 2; hh++)
                    s_max[wm + t * 16 + g + hh * 8][nw] = mx[t][hh];
        }
        __syncthreads();
#pragma unroll
        for (int t = 0; t < 2; t++)
#pragma unroll
            for (int hh = 0; hh < 2; hh++) {
                int row = wm + t * 16 + g + hh * 8;
                mx[t][hh] = fmaxf(fmaxf(s_max[row][0], s_max[row][1]),
                                  fmaxf(s_max[row][2], s_max[row][3]));
            }
        float sm[2][2] = {{0.f, 0.f}, {0.f, 0.f}};
#pragma unroll
        for (int t = 0; t < 2; t++)
#pragma unroll
            for (int n = 0; n < 5; n++)
#pragma unroll
                for (int v = 0; v < 4; v++) {
                    float e = expf(c[t][n][v] - mx[t][v >> 1]);
                    c[t][n][v] = e;
                    sm[t][v >> 1] += e;
                }
#pragma unroll
        for (int t = 0; t < 2; t++)
#pragma unroll
            for (int hh = 0; hh < 2; hh++) {
                float s = sm[t][hh];
                s += __shfl_xor_sync(0xffffffffu, s, 1);
                s += __shfl_xor_sync(0xffffffffu, s, 2);
                sm[t][hh] = s;
            }
        if (qd == 0) {
#pragma unroll
            for (int t = 0; t < 2; t++)
#pragma unroll
                for (int hh = 0; hh < 2; hh++)
                    s_sum[wm + t * 16 + g + hh * 8][nw] = sm[t][hh];
        }
        __syncthreads();
        __half* Ps = reinterpret_cast<__half*>(smc + PS_OFF);
        float inv[2][2];
#pragma unroll
        for (int t = 0; t < 2; t++)
#pragma unroll
            for (int hh = 0; hh < 2; hh++) {
                int row = wm + t * 16 + g + hh * 8;
                inv[t][hh] = 1.f / (s_sum[row][0] + s_sum[row][1]
                                    + s_sum[row][2] + s_sum[row][3]);
            }
#pragma unroll
        for (int t = 0; t < 2; t++)
#pragma unroll
            for (int n = 0; n < 5; n++) {
                int col = wn + n * 8 + 2 * qd;
                if (col < 144) {
#pragma unroll
                    for (int hh = 0; hh < 2; hh++) {
                        int row = wm + t * 16 + g + hh * 8;
                        __half2 p = __floats2half2_rn(c[t][n][2 * hh] * inv[t][hh],
                                                      c[t][n][2 * hh + 1] * inv[t][hh]);
                        *reinterpret_cast<__half2*>(&Ps[row * PS_STR + col]) = p;
                    }
                }
            }
    }
    __syncthreads();

    // ---- phase 3: heads. Whole-tile V double buffering ----
    {
        const int wm3 = (wid & 1) * 32;
        const int wn3 = (wid >> 1) * 32;
        const uint32_t ps_base = smb + PS_OFF;

        uint32_t aoff[2];
#pragma unroll
        for (int t = 0; t < 2; t++)
            aoff[t] = (uint32_t)(((wm3 + t * 16 + ((lane >> 3) & 1) * 8 + lr) * PS_STR
                                  + (lane >> 4) * 8) * 2);
        const int tk = lr + ((lane >> 3) & 1) * 8;
        const int tn = (lane >> 4) * 8;

        for (int nt = 0; nt < 4; nt++) {
            cp_wait0();
            __syncthreads();
            if (nt + 1 < 4) {
                vload_tile((nt + 1) & 1, (nt + 1) * 128);
                cp_commit();
            }
            uint32_t vbse = smb + (uint32_t)((nt & 1) * HV_TILE);
            const int n0 = nt * 128;

            float cc[2][4][4];
#pragma unroll
            for (int t = 0; t < 2; t++)
#pragma unroll
                for (int n = 0; n < 4; n++)
#pragma unroll
                    for (int v = 0; v < 4; v++) cc[t][n][v] = 0.f;

#pragma unroll
            for (int it = 0; it < 9; ++it) {
                uint32_t a[2][4], bfr[4][2];
#pragma unroll
                for (int t = 0; t < 2; t++)
                    ldsm_x4(a[t][0], a[t][1], a[t][2], a[t][3],
                            ps_base + aoff[t] + it * 32);
#pragma unroll
                for (int p = 0; p < 2; p++) {
                    uint32_t r0, r1, r2, r3;
                    ldsm_x4_t(r0, r1, r2, r3,
                              vbse + (uint32_t)(((it * 16 + tk) * 136
                                                 + wn3 + p * 16 + tn) * 2));
                    bfr[2 * p][0] = r0;     bfr[2 * p][1] = r1;
                    bfr[2 * p + 1][0] = r2; bfr[2 * p + 1][1] = r3;
                }
#pragma unroll
                for (int t = 0; t < 2; t++)
#pragma unroll
                    for (int n = 0; n < 4; n++)
                        mma_f16(cc[t][n], a[t], bfr[n]);
            }

#pragma unroll
            for (int t = 0; t < 2; t++) {
#pragma unroll
                for (int n = 0; n < 4; n++) {
                    int col = n0 + wn3 + n * 8 + 2 * qd;
                    int i0r = m0 + wm3 + t * 16 + g;
                    __half2 p0 = __floats2half2_rn(cc[t][n][0], cc[t][n][1]);
                    __half2 p1 = __floats2half2_rn(cc[t][n][2], cc[t][n][3]);
                    *reinterpret_cast<__half2*>(X + ((size_t)b * Gc + i0r) * 512 + col) = p0;
                    *reinterpret_cast<__half2*>(X + ((size_t)b * Gc + i0r + 8) * 512 + col) = p1;
                }
            }
        }
    }
}

// ---------------------------------------------------------------------------
// Launch (multi-stream fork: cvt-h overlaps tiny2 + qM)
// ---------------------------------------------------------------------------
extern "C" void kernel_launch(void* const* d_in, const int* in_sizes, int n_in,
                              void* d_out, int out_size) {
    const float* q    = (const float*)d_in[0];
    const int*   mask = (const int*)d_in[1];
    const float* h    = (const float*)d_in[4];
    const float* Wq   = (const float*)d_in[5];
    const float* Wk   = (const float*)d_in[6];
    const float* Wv   = (const float*)d_in[7];
    const float* Wo   = (const float*)d_in[8];
    const float* bo   = (const float*)d_in[9];
    float* out = (float*)d_out;

    __half *gq16, *gh16, *gQp, *gX16, *gW16, *gWM16;
    cudaGetSymbolAddress((void**)&gq16, g_q16);
    cudaGetSymbolAddress((void**)&gh16, g_h16);
    cudaGetSymbolAddress((void**)&gQp,  g_Qp);
    cudaGetSymbolAddress((void**)&gX16, g_X16);
    cudaGetSymbolAddress((void**)&gW16, g_W16);
    cudaGetSymbolAddress((void**)&gWM16, g_WM16);
    __half* gWqT = gW16;
    __half* gWkT = gW16 + 1 * 512 * 512;
    __half* gWvT = gW16 + 2 * 512 * 512;
    __half* gWo_ = gW16 + 3 * 512 * 512;
    __half* gWm  = gWM16;                  // Wm[i,k] = sum_j Wk[j,i] Wq[j,k]
    __half* gWn  = gWM16 + 512 * 512;      // Wn[j,i] = sum_k Wo[j,k] Wv[k,i]

    static cudaStream_t s2 = nullptr;
    static cudaEvent_t evF = nullptr, evJ = nullptr;
    if (!s2) {
        cudaStreamCreateWithFlags(&s2, cudaStreamNonBlocking);
        cudaEventCreateWithFlags(&evF, cudaEventDisableTiming);
        cudaEventCreateWithFlags(&evJ, cudaEventDisableTiming);
        cudaFuncSetAttribute(mma_gemm_f16<false>,
                             cudaFuncAttributeMaxDynamicSharedMemorySize, GM_SMEM);
        cudaFuncSetAttribute(mma_gemm_f16<true>,
                             cudaFuncAttributeMaxDynamicSharedMemorySize, GM_SMEM);
        cudaFuncSetAttribute(tiny2_gemm_f16,
                             cudaFuncAttributeMaxDynamicSharedMemorySize, GM_SMEM);
        cudaFuncSetAttribute(attention_kernel,
                             cudaFuncAttributeMaxDynamicSharedMemorySize, AT_DYN);
    }

    int n8 = (MTOT * 512) / 8;

    // fork: cvt h on side stream (only attention needs it)
    cudaEventRecord(evF, 0);
    cudaStreamWaitEvent(s2, evF, 0);
    cvt_h_kernel<<<4096, 256, 0, s2>>>((const float4*)h, (uint4*)gh16, n8);
    cudaEventRecord(evJ, s2);

    // main stream: cvt q + weight prep -> folds -> qM
    prep_qw_kernel<<<dim3(16, 16, 5), dim3(32, 8)>>>(
        (const float4*)q, (uint4*)gq16, Wq, Wk, Wv, Wo, gW16, n8);
    tiny2_gemm_f16<<<dim3(4, 4, 2), 512, GM_SMEM>>>(gWkT, gWqT, gWm,
                                                    gWo_, gWvT, gWn);
    mma_gemm_f16<false><<<dim3(4, MTOT / 128), 512, GM_SMEM>>>(
        gq16, gWm, nullptr, gQp, 512);

    // join: attention needs h16
    cudaStreamWaitEvent(0, evJ, 0);
    attention_kernel<<<dim3(3, Bc), 256, AT_DYN>>>(gQp, gh16, mask, gX16);

    // out = X @ Wn^T + bias
    mma_gemm_f16<true><<<dim3(4, MTOT / 128), 512, GM_SMEM>>>(
        gX16, gWn, bo, out, 512);
}

// round 15
// speedup vs baseline: 1.0386x; 1.0386x over previous
#include <cuda_runtime.h>
#include <cuda_fp16.h>
#include <math.h>
#include <stdint.h>

// ---------------------------------------------------------------------------
// Problem constants
// ---------------------------------------------------------------------------
constexpr int Bc   = 512;
constexpr int Gc   = 131;
constexpr int MTOT = Bc * Gc;      // 67072
constexpr int LEAF_LO = 80;
constexpr int LEAF_HI = 130;

// Scratch (device globals: allocation-free)
__device__ __half g_q16[(size_t)MTOT * 512];    // q  (fp16)
__device__ __half g_h16[(size_t)MTOT * 512];    // h  (fp16)
__device__ __half g_Qp [(size_t)MTOT * 512];    // q' = q·M
__device__ __half g_X16[(size_t)MTOT * 512];    // X  = attn·h
__device__ __half g_W16[4][512 * 512];          // WqT, WkT, WvT, Wo (fp16)
__device__ __half g_WM16[2][512 * 512];         // Wm, Wn (folded, fp16)

// ---------------------------------------------------------------------------
// PTX helpers (baseline sm_75/80 PTX — valid for compute_103)
// ---------------------------------------------------------------------------
__device__ __forceinline__ uint32_t smem_u32(const void* p) {
    return (uint32_t)__cvta_generic_to_shared(p);
}
__device__ __forceinline__ void cp_async16(uint32_t sdst, const void* gsrc) {
    asm volatile("cp.async.cg.shared.global [%0], [%1], 16;" :: "r"(sdst), "l"(gsrc));
}
__device__ __forceinline__ void cp_async16z(uint32_t sdst, const void* gsrc, bool valid) {
    int sz = valid ? 16 : 0;
    asm volatile("cp.async.cg.shared.global [%0], [%1], 16, %2;"
                 :: "r"(sdst), "l"(gsrc), "r"(sz));
}
__device__ __forceinline__ void cp_commit() { asm volatile("cp.async.commit_group;"); }
__device__ __forceinline__ void cp_wait0()  { asm volatile("cp.async.wait_group 0;"); }
__device__ __forceinline__ void cp_wait1()  { asm volatile("cp.async.wait_group 1;"); }

__device__ __forceinline__ void ldsm_x4(uint32_t& r0, uint32_t& r1, uint32_t& r2,
                                        uint32_t& r3, uint32_t addr) {
    asm volatile("ldmatrix.sync.aligned.m8n8.x4.shared.b16 {%0,%1,%2,%3}, [%4];"
                 : "=r"(r0), "=r"(r1), "=r"(r2), "=r"(r3) : "r"(addr));
}
__device__ __forceinline__ void ldsm_x4_t(uint32_t& r0, uint32_t& r1, uint32_t& r2,
                                          uint32_t& r3, uint32_t addr) {
    asm volatile("ldmatrix.sync.aligned.m8n8.x4.trans.shared.b16 {%0,%1,%2,%3}, [%4];"
                 : "=r"(r0), "=r"(r1), "=r"(r2), "=r"(r3) : "r"(addr));
}
__device__ __forceinline__ void mma_f16(float* c, const uint32_t* a, const uint32_t* b) {
    asm volatile(
        "mma.sync.aligned.m16n8k16.row.col.f32.f16.f16.f32 "
        "{%0,%1,%2,%3}, {%4,%5,%6,%7}, {%8,%9}, {%0,%1,%2,%3};"
        : "+f"(c[0]), "+f"(c[1]), "+f"(c[2]), "+f"(c[3])
        : "r"(a[0]), "r"(a[1]), "r"(a[2]), "r"(a[3]), "r"(b[0]), "r"(b[1]));
}

// ---------------------------------------------------------------------------
// cvt fp32 -> fp16, 8 elems/thread/iter (runs on side streams for q and h)
// ---------------------------------------------------------------------------
__global__ void cvt_f16_kernel(const float4* __restrict__ in,
                               uint4* __restrict__ out, int n8) {
    int i = blockIdx.x * blockDim.x + threadIdx.x;
    int stride = gridDim.x * blockDim.x;
    for (; i < n8; i += stride) {
        float4 v0 = in[2 * i], v1 = in[2 * i + 1];
        __half2 h0 = __floats2half2_rn(v0.x, v0.y);
        __half2 h1 = __floats2half2_rn(v0.z, v0.w);
        __half2 h2 = __floats2half2_rn(v1.x, v1.y);
        __half2 h3 = __floats2half2_rn(v1.z, v1.w);
        uint4 o;
        o.x = *reinterpret_cast<uint32_t*>(&h0);
        o.y = *reinterpret_cast<uint32_t*>(&h1);
        o.z = *reinterpret_cast<uint32_t*>(&h2);
        o.w = *reinterpret_cast<uint32_t*>(&h3);
        out[i] = o;
    }
}

// weight prep only: z=0..2 transpose+cvt Wq/Wk/Wv; z=3 plain cvt Wo
__global__ void prep_w_kernel(const float* __restrict__ w0, const float* __restrict__ w1,
                              const float* __restrict__ w2, const float* __restrict__ w3,
                              __half* __restrict__ out) {
    __shared__ float tile[32][33];
    const int z = blockIdx.z;
    const float* in = (z == 0) ? w0 : (z == 1) ? w1 : (z == 2) ? w2 : w3;
    __half* o = out + (size_t)z * 512 * 512;
    const int tx = threadIdx.x, ty = threadIdx.y;
    const int x = blockIdx.x * 32 + tx;
    const int y0 = blockIdx.y * 32;
    if (z < 3) {
#pragma unroll
        for (int j = 0; j < 32; j += 8)
            tile[ty + j][tx] = in[(size_t)(y0 + ty + j) * 512 + x];
        __syncthreads();
        const int x2 = y0 + tx;
        const int y2 = blockIdx.x * 32;
#pragma unroll
        for (int j = 0; j < 32; j += 8)
            o[(size_t)(y2 + ty + j) * 512 + x2] = __float2half_rn(tile[tx][ty + j]);
    } else {
#pragma unroll
        for (int j = 0; j < 32; j += 8)
            o[(size_t)(y0 + ty + j) * 512 + x] =
                __float2half_rn(in[(size_t)(y0 + ty + j) * 512 + x]);
    }
}

// ---------------------------------------------------------------------------
// fp16 mma GEMM-NT, 512 threads (16 warps, 4m x 4n, warp tile 32x32):
// C[M,N] = A[M,512] @ W[N,512]^T. BM=BN=128, BK=64, 3-stage pipeline.
// ---------------------------------------------------------------------------
constexpr int GM_ROWH = 72;
constexpr int GM_STAGE_B = 256 * GM_ROWH * 2;     // 36864
constexpr int GM_STAGES = 3;
constexpr int GM_SMEM = GM_STAGES * GM_STAGE_B;   // 110592
constexpr int GM_ITERS = 8;

template <bool OUTF32>
__device__ __forceinline__ void gemm_body_f16(const __half* __restrict__ A,
                                              const __half* __restrict__ W,
                                              const float* __restrict__ bias,
                                              void* __restrict__ Cv, int CS,
                                              int bm, int bn) {
    extern __shared__ __align__(16) char smraw[];
    const uint32_t smb = smem_u32(smraw);
    const int tid = threadIdx.x;
    const int wid = tid >> 5;
    const int lane = tid & 31;
    const int wm = (wid & 3) * 32;
    const int wn = (wid >> 2) * 32;

    const __half* Ag = A + (size_t)bm * 512;
    const __half* Wg = W + (size_t)bn * 512;

    float c[2][4][4];
#pragma unroll
    for (int t = 0; t < 2; t++)
#pragma unroll
        for (int n = 0; n < 4; n++)
#pragma unroll
            for (int v = 0; v < 4; v++) c[t][n][v] = 0.f;

    const int lr = lane & 7;
    uint32_t aoff[2], boff[2];
#pragma unroll
    for (int t = 0; t < 2; t++)
        aoff[t] = (uint32_t)(((wm + t * 16 + ((lane >> 3) & 1) * 8 + lr) * GM_ROWH
                              + (lane >> 4) * 8) * 2);
#pragma unroll
    for (int jp = 0; jp < 2; jp++)
        boff[jp] = (uint32_t)(128 * GM_ROWH * 2
                              + ((wn + jp * 16 + ((lane >> 4) & 1) * 8 + lr) * GM_ROWH
                                 + ((lane >> 3) & 1) * 8) * 2);

    auto load_stage = [&](int s, int k0) {
        uint32_t base = smb + (uint32_t)(s * GM_STAGE_B);
#pragma unroll
        for (int i = 0; i < 2; i++) {
            int id = tid + i * 512;
            int row = id >> 3, c8 = (id & 7) << 3;
            cp_async16(base + (uint32_t)((row * GM_ROWH + c8) * 2),
                       Ag + (size_t)row * 512 + k0 + c8);
        }
#pragma unroll
        for (int i = 0; i < 2; i++) {
            int id = tid + i * 512;
            int row = id >> 3, c8 = (id & 7) << 3;
            cp_async16(base + (uint32_t)(((128 + row) * GM_ROWH + c8) * 2),
                       Wg + (size_t)row * 512 + k0 + c8);
        }
    };

    load_stage(0, 0);    cp_commit();
    load_stage(1, 64);   cp_commit();
    cp_wait1();
    __syncthreads();

    int sc = 0, sl = 2;
    for (int it = 0; it < GM_ITERS; ++it) {
        if (it + 2 < GM_ITERS) {
            load_stage(sl, (it + 2) * 64);
            cp_commit();
            sl = (sl == GM_STAGES - 1) ? 0 : sl + 1;
        }
        uint32_t base = smb + (uint32_t)(sc * GM_STAGE_B);
        sc = (sc == GM_STAGES - 1) ? 0 : sc + 1;
#pragma unroll
        for (int kk = 0; kk < 4; kk++) {
            uint32_t a[2][4], b[4][2];
#pragma unroll
            for (int t = 0; t < 2; t++)
                ldsm_x4(a[t][0], a[t][1], a[t][2], a[t][3], base + aoff[t] + kk * 32);
#pragma unroll
            for (int jp = 0; jp < 2; jp++) {
                uint32_t r0, r1, r2, r3;
                ldsm_x4(r0, r1, r2, r3, base + boff[jp] + kk * 32);
                b[2 * jp][0] = r0;     b[2 * jp][1] = r1;
                b[2 * jp + 1][0] = r2; b[2 * jp + 1][1] = r3;
            }
#pragma unroll
            for (int t = 0; t < 2; t++)
#pragma unroll
                for (int n = 0; n < 4; n++)
                    mma_f16(c[t][n], a[t], b[n]);
        }
        if (it + 2 < GM_ITERS)      cp_wait1();
        else if (it + 1 < GM_ITERS) cp_wait0();
        __syncthreads();
    }

    const int g = lane >> 2;
    const int q = lane & 3;
#pragma unroll
    for (int n = 0; n < 4; n++) {
        int col = bn + wn + n * 8 + 2 * q;
        float b0 = 0.f, b1 = 0.f;
        if (OUTF32) { b0 = bias[col]; b1 = bias[col + 1]; }
#pragma unroll
        for (int t = 0; t < 2; t++) {
            int row0 = bm + wm + t * 16 + g;
            if (OUTF32) {
                float* Cf = (float*)Cv;
                *reinterpret_cast<float2*>(Cf + (size_t)row0 * CS + col) =
                    make_float2(c[t][n][0] + b0, c[t][n][1] + b1);
                *reinterpret_cast<float2*>(Cf + (size_t)(row0 + 8) * CS + col) =
                    make_float2(c[t][n][2] + b0, c[t][n][3] + b1);
            } else {
                __half* Ch = (__half*)Cv;
                __half2 p0 = __floats2half2_rn(c[t][n][0], c[t][n][1]);
                __half2 p1 = __floats2half2_rn(c[t][n][2], c[t][n][3]);
                *reinterpret_cast<__half2*>(Ch + (size_t)row0 * CS + col) = p0;
                *reinterpret_cast<__half2*>(Ch + (size_t)(row0 + 8) * CS + col) = p1;
            }
        }
    }
}

template <bool OUTF32>
__global__ void __launch_bounds__(512, 2)
mma_gemm_f16(const __half* __restrict__ A, const __half* __restrict__ W,
             const float* __restrict__ bias, void* __restrict__ C, int CS) {
    gemm_body_f16<OUTF32>(A, W, bias, C, CS, blockIdx.y * 128, blockIdx.x * 128);
}

__global__ void __launch_bounds__(512, 2)
tiny2_gemm_f16(const __half* __restrict__ A0, const __half* __restrict__ W0,
               __half* __restrict__ C0,
               const __half* __restrict__ A1, const __half* __restrict__ W1,
               __half* __restrict__ C1) {
    if (blockIdx.z == 0)
        gemm_body_f16<false>(A0, W0, nullptr, C0, 512, blockIdx.y * 128, blockIdx.x * 128);
    else
        gemm_body_f16<false>(A1, W1, nullptr, C1, 512, blockIdx.y * 128, blockIdx.x * 128);
}

// ---------------------------------------------------------------------------
// FUSED attention (round-13 proven version). grid (3, Bc):
//   x<2 -> 64-row mma tile; x==2 -> tail rows 128..130.
// Smem (dynamic, 97792 B):
//   region A [0, 78336): phase1 2x33408 scores pipeline -> fp32 stash
//                        Ss[64][164] -> phase3 2x39168 whole-tile V buffers
//   Ps at [78336, +19456): fp16 probs [64][152]
// ---------------------------------------------------------------------------
constexpr int SC_QB   = 64 * 72 * 2;              // 9216
constexpr int SC_STG  = SC_QB + 168 * 72 * 2;     // 33408
constexpr int HV_TILE = 144 * 136 * 2;            // 39168 whole V n-tile
constexpr int PS_OFF  = 2 * HV_TILE;              // 78336
constexpr int PS_STR  = 152;
constexpr int AT_DYN  = PS_OFF + 64 * PS_STR * 2; // 97792

__global__ void __launch_bounds__(256)
attention_kernel(const __half* __restrict__ Q, const __half* __restrict__ Hm,
                 const int* __restrict__ mask, __half* __restrict__ X) {
    extern __shared__ __align__(16) char smc[];
    __shared__ int mask_s[144];
    const uint32_t smb = smem_u32(smc);
    const int tid = threadIdx.x;
    const int wid = tid >> 5;
    const int lane = tid & 31;
    const int b = blockIdx.y;

    // ======================= TAIL CTA (rows 128..130) =======================
    if (blockIdx.x == 2) {
        float* qs = reinterpret_cast<float*>(smc);           // [3][512]
        float* ps = reinterpret_cast<float*>(smc + 6144);    // [3][132]
        int*   mk = reinterpret_cast<int*>(smc + 7808);      // [132]
        const __half* Qb = Q  + ((size_t)b * Gc + 128) * 512;
        const __half* hb = Hm + (size_t)b * Gc * 512;

        for (int i = tid; i < 3 * 512; i += 256) qs[i] = __half2float(Qb[i]);
        if (tid < 132) mk[tid] = (tid < Gc) ? mask[b * Gc + tid] : 1;
        __syncthreads();

        for (int j = wid; j < Gc; j += 8) {
            const __half* hj = hb + (size_t)j * 512;
            float a0 = 0.f, a1 = 0.f, a2 = 0.f;
#pragma unroll
            for (int k = 0; k < 16; k++) {
                int idx = lane + k * 32;
                float hv = __half2float(hj[idx]);
                a0 = fmaf(hv, qs[idx], a0);
                a1 = fmaf(hv, qs[512 + idx], a1);
                a2 = fmaf(hv, qs[1024 + idx], a2);
            }
#pragma unroll
            for (int o = 16; o; o >>= 1) {
                a0 += __shfl_xor_sync(0xffffffffu, a0, o);
                a1 += __shfl_xor_sync(0xffffffffu, a1, o);
                a2 += __shfl_xor_sync(0xffffffffu, a2, o);
            }
            if (lane == 0) { ps[j] = a0; ps[132 + j] = a1; ps[264 + j] = a2; }
        }
        __syncthreads();

        if (wid < 3) {
            const int gi = 128 + wid;
            const bool li = (gi >= LEAF_LO) && (gi < LEAF_HI);
            const float norm = 0.04419417382415922f;
            float v[5];
            float mx = -3.0e38f;
#pragma unroll
            for (int ch = 0; ch < 5; ch++) {
                int j = lane + ch * 32;
                float val = -3.0e38f;
                if (j < Gc) {
                    bool mj = (mk[j] > 0) || (li && j >= LEAF_LO && j < LEAF_HI);
                    val = mj ? -30.f : ps[wid * 132 + j] * norm;
                }
                v[ch] = val;
                mx = fmaxf(mx, val);
            }
#pragma unroll
            for (int o = 16; o; o >>= 1) mx = fmaxf(mx, __shfl_xor_sync(0xffffffffu, mx, o));
            float e[5];
            float sum = 0.f;
#pragma unroll
            for (int ch = 0; ch < 5; ch++) {
                int j = lane + ch * 32;
                e[ch] = (j < Gc) ? expf(v[ch] - mx) : 0.f;
                sum += e[ch];
            }
#pragma unroll
            for (int o = 16; o; o >>= 1) sum += __shfl_xor_sync(0xffffffffu, sum, o);
            float inv = 1.f / sum;
#pragma unroll
            for (int ch = 0; ch < 5; ch++) {
                int j = lane + ch * 32;
                if (j < Gc) {
                    bool mj = (mk[j] > 0) || (li && j >= LEAF_LO && j < LEAF_HI);
                    ps[wid * 132 + j] = mj ? 0.f : e[ch] * inv;
                }
            }
        }
        __syncthreads();

        float acc[3][2] = {{0.f, 0.f}, {0.f, 0.f}, {0.f, 0.f}};
        for (int j = 0; j < Gc; j++) {
            float p0 = ps[j], p1 = ps[132 + j], p2 = ps[264 + j];
            float h0 = __half2float(hb[(size_t)j * 512 + tid]);
            float h1 = __half2float(hb[(size_t)j * 512 + tid + 256]);
            acc[0][0] = fmaf(p0, h0, acc[0][0]); acc[0][1] = fmaf(p0, h1, acc[0][1]);
            acc[1][0] = fmaf(p1, h0, acc[1][0]); acc[1][1] = fmaf(p1, h1, acc[1][1]);
            acc[2][0] = fmaf(p2, h0, acc[2][0]); acc[2][1] = fmaf(p2, h1, acc[2][1]);
        }
        __half* Xb = X + ((size_t)b * Gc + 128) * 512;
#pragma unroll
        for (int i = 0; i < 3; i++) {
            Xb[(size_t)i * 512 + tid]       = __float2half_rn(acc[i][0]);
            Xb[(size_t)i * 512 + tid + 256] = __float2half_rn(acc[i][1]);
        }
        return;
    }

    // ======================= MAIN CTA (64 rows) =============================
    const int m0 = blockIdx.x * 64;
    if (tid < 144) mask_s[tid] = (tid < Gc) ? mask[b * Gc + tid] : 1;

    const __half* Qb = Q  + (size_t)b * Gc * 512;
    const __half* Kb = Hm + (size_t)b * Gc * 512;

    // ---- phase 1: scores (fp16 mma), 2-stage pipeline, K=512 = 8 x 64 ----
    {
        const int wm = (wid & 1) * 32;
        const int wn = (wid >> 1) * 40;
        const int lr = lane & 7;

        float c[2][5][4];
#pragma unroll
        for (int t = 0; t < 2; t++)
#pragma unroll
            for (int n = 0; n < 5; n++)
#pragma unroll
                for (int v = 0; v < 4; v++) c[t][n][v] = 0.f;

        uint32_t aoff[2], boff[3];
#pragma unroll
        for (int t = 0; t < 2; t++)
            aoff[t] = (uint32_t)(((wm + t * 16 + ((lane >> 3) & 1) * 8 + lr) * 72
                                  + (lane >> 4) * 8) * 2);
#pragma unroll
        for (int jp = 0; jp < 3; jp++)
            boff[jp] = (uint32_t)(SC_QB
                                  + ((wn + jp * 16 + ((lane >> 4) & 1) * 8 + lr) * 72
                                     + ((lane >> 3) & 1) * 8) * 2);

        auto load_stage = [&](int s, int k0) {
            uint32_t qb = smb + (uint32_t)(s * SC_STG);
            uint32_t kb = qb + SC_QB;
#pragma unroll
            for (int l = 0; l < 2; l++) {
                int id = tid + l * 256;
                int row = id >> 3, c8 = (id & 7) << 3;
                cp_async16(qb + (uint32_t)((row * 72 + c8) * 2),
                           Qb + (size_t)(m0 + row) * 512 + k0 + c8);
            }
#pragma unroll
            for (int i = 0; i < 5; i++) {
                int id = tid + i * 256;
                int row = id >> 3, c8 = (id & 7) << 3;
                bool v = row < Gc;
                const __half* src = v ? Kb + (size_t)row * 512 + k0 + c8 : Kb;
                cp_async16z(kb + (uint32_t)((row * 72 + c8) * 2), src, v);
            }
        };

        load_stage(0, 0);
        cp_commit();
        cp_wait0();
        __syncthreads();

        for (int it = 0; it < 8; ++it) {
            if (it + 1 < 8) {
                load_stage((it + 1) & 1, (it + 1) * 64);
                cp_commit();
            }
            uint32_t qb = smb + (uint32_t)((it & 1) * SC_STG);
#pragma unroll
            for (int kk = 0; kk < 4; kk++) {
                uint32_t a[2][4], bfr[6][2];
#pragma unroll
                for (int t = 0; t < 2; t++)
                    ldsm_x4(a[t][0], a[t][1], a[t][2], a[t][3], qb + aoff[t] + kk * 32);
#pragma unroll
                for (int jp = 0; jp < 3; jp++) {
                    uint32_t r0, r1, r2, r3;
                    ldsm_x4(r0, r1, r2, r3, qb + boff[jp] + kk * 32);
                    bfr[2 * jp][0] = r0;     bfr[2 * jp][1] = r1;
                    bfr[2 * jp + 1][0] = r2; bfr[2 * jp + 1][1] = r3;
                }
#pragma unroll
                for (int t = 0; t < 2; t++)
#pragma unroll
                    for (int n = 0; n < 5; n++)
                        mma_f16(c[t][n], a[t], bfr[n]);
            }
            if (it + 1 < 8) cp_wait0();
            __syncthreads();
        }

        // stash accumulators fp32 (reuse pipeline region): Ss[64][164]
        float* Ss = reinterpret_cast<float*>(smc);
        const int g = lane >> 2;
        const int qd = lane & 3;
#pragma unroll
        for (int t = 0; t < 2; t++) {
            int r0 = wm + t * 16 + g;
#pragma unroll
            for (int n = 0; n < 5; n++) {
                int col = wn + n * 8 + 2 * qd;
                *reinterpret_cast<float2*>(&Ss[r0 * 164 + col]) =
                    make_float2(c[t][n][0], c[t][n][1]);
                *reinterpret_cast<float2*>(&Ss[(r0 + 8) * 164 + col]) =
                    make_float2(c[t][n][2], c[t][n][3]);
            }
        }
    }
    __syncthreads();

    // ---- phase 2: softmax -> Ps[64][152] fp16 ----
    {
        float* Ss = reinterpret_cast<float*>(smc);
        __half* Ps = reinterpret_cast<__half*>(smc + PS_OFF);
        const float norm = 0.04419417382415922f;
#pragma unroll
        for (int rr = 0; rr < 8; rr++) {
            int i_loc = wid * 8 + rr;
            int gi = m0 + i_loc;                    // < 128
            bool li = (gi >= LEAF_LO) && (gi < LEAF_HI);
            float v[5];
            float mx = -3.0e38f;
#pragma unroll
            for (int ch = 0; ch < 5; ch++) {
                int j = lane + ch * 32;
                float val = -3.0e38f;
                if (j < Gc) {
                    float s = Ss[i_loc * 164 + j] * norm;
                    bool mj = (mask_s[j] > 0) || (li && j >= LEAF_LO && j < LEAF_HI);
                    val = mj ? -30.f : s;
                }
                v[ch] = val;
                mx = fmaxf(mx, val);
            }
#pragma unroll
            for (int o = 16; o; o >>= 1) mx = fmaxf(mx, __shfl_xor_sync(0xffffffffu, mx, o));
            float e[5];
            float sum = 0.f;
#pragma unroll
            for (int ch = 0; ch < 5; ch++) {
                int j = lane + ch * 32;
                e[ch] = (j < Gc) ? expf(v[ch] - mx) : 0.f;
                sum += e[ch];
            }
#pragma unroll
            for (int o = 16; o; o >>= 1) sum += __shfl_xor_sync(0xffffffffu, sum, o);
            float inv = 1.f / sum;
#pragma unroll
            for (int ch = 0; ch < 5; ch++) {
                int j = lane + ch * 32;
                if (j < 144) {
                    float p = 0.f;
                    if (j < Gc) {
                        bool mj = (mask_s[j] > 0) || (li && j >= LEAF_LO && j < LEAF_HI);
                        p = mj ? 0.f : e[ch] * inv;
                    }
                    Ps[i_loc * PS_STR + j] = __float2half_rn(p);
                }
            }
        }
    }
    __syncthreads();

    // ---- phase 3: heads. Whole-tile V double buffering ----
    {
        const __half* Vb = Hm + (size_t)b * Gc * 512;
        const int wm = (wid & 1) * 32;
        const int wn = (wid >> 1) * 32;
        const int lr = lane & 7;
        const uint32_t ps_base = smb + PS_OFF;

        uint32_t aoff[2];
#pragma unroll
        for (int t = 0; t < 2; t++)
            aoff[t] = (uint32_t)(((wm + t * 16 + ((lane >> 3) & 1) * 8 + lr) * PS_STR
                                  + (lane >> 4) * 8) * 2);
        const int tk = lr + ((lane >> 3) & 1) * 8;
        const int tn = (lane >> 4) * 8;

        auto vload_tile = [&](int s, int n0) {
            uint32_t vbse = smb + (uint32_t)(s * HV_TILE);
#pragma unroll
            for (int i = 0; i < 9; i++) {
                int id = tid + i * 256;
                int row = id >> 4, c8 = (id & 15) << 3;
                bool v = row < Gc;
                const __half* src = v ? Vb + (size_t)row * 512 + n0 + c8 : Vb;
                cp_async16z(vbse + (uint32_t)((row * 136 + c8) * 2), src, v);
            }
        };

        vload_tile(0, 0);
        cp_commit();

        for (int nt = 0; nt < 4; nt++) {
            cp_wait0();
            __syncthreads();
            if (nt + 1 < 4) {
                vload_tile((nt + 1) & 1, (nt + 1) * 128);
                cp_commit();
            }
            uint32_t vbse = smb + (uint32_t)((nt & 1) * HV_TILE);
            const int n0 = nt * 128;

            float c[2][4][4];
#pragma unroll
            for (int t = 0; t < 2; t++)
#pragma unroll
                for (int n = 0; n < 4; n++)
#pragma unroll
                    for (int v = 0; v < 4; v++) c[t][n][v] = 0.f;

#pragma unroll
            for (int it = 0; it < 9; ++it) {
                uint32_t a[2][4], bfr[4][2];
#pragma unroll
                for (int t = 0; t < 2; t++)
                    ldsm_x4(a[t][0], a[t][1], a[t][2], a[t][3],
                            ps_base + aoff[t] + it * 32);
#pragma unroll
                for (int p = 0; p < 2; p++) {
                    uint32_t r0, r1, r2, r3;
                    ldsm_x4_t(r0, r1, r2, r3,
                              vbse + (uint32_t)(((it * 16 + tk) * 136
                                                 + wn + p * 16 + tn) * 2));
                    bfr[2 * p][0] = r0;     bfr[2 * p][1] = r1;
                    bfr[2 * p + 1][0] = r2; bfr[2 * p + 1][1] = r3;
                }
#pragma unroll
                for (int t = 0; t < 2; t++)
#pragma unroll
                    for (int n = 0; n < 4; n++)
                        mma_f16(c[t][n], a[t], bfr[n]);
            }

            const int g = lane >> 2;
            const int qd = lane & 3;
#pragma unroll
            for (int t = 0; t < 2; t++) {
#pragma unroll
                for (int n = 0; n < 4; n++) {
                    int col = n0 + wn + n * 8 + 2 * qd;
                    int i0r = m0 + wm + t * 16 + g;
                    __half2 p0 = __floats2half2_rn(c[t][n][0], c[t][n][1]);
                    __half2 p1 = __floats2half2_rn(c[t][n][2], c[t][n][3]);
                    *reinterpret_cast<__half2*>(X + ((size_t)b * Gc + i0r) * 512 + col) = p0;
                    *reinterpret_cast<__half2*>(X + ((size_t)b * Gc + i0r + 8) * 512 + col) = p1;
                }
            }
        }
    }
}

// ---------------------------------------------------------------------------
// Launch: 3-way fork. s2: cvt q; s3: cvt h; main: weights -> tiny2 ->
// [join q] qM -> [join h] attention -> out.
// ---------------------------------------------------------------------------
extern "C" void kernel_launch(void* const* d_in, const int* in_sizes, int n_in,
                              void* d_out, int out_size) {
    const float* q    = (const float*)d_in[0];
    const int*   mask = (const int*)d_in[1];
    const float* h    = (const float*)d_in[4];
    const float* Wq   = (const float*)d_in[5];
    const float* Wk   = (const float*)d_in[6];
    const float* Wv   = (const float*)d_in[7];
    const float* Wo   = (const float*)d_in[8];
    const float* bo   = (const float*)d_in[9];
    float* out = (float*)d_out;

    __half *gq16, *gh16, *gQp, *gX16, *gW16, *gWM16;
    cudaGetSymbolAddress((void**)&gq16, g_q16);
    cudaGetSymbolAddress((void**)&gh16, g_h16);
    cudaGetSymbolAddress((void**)&gQp,  g_Qp);
    cudaGetSymbolAddress((void**)&gX16, g_X16);
    cudaGetSymbolAddress((void**)&gW16, g_W16);
    cudaGetSymbolAddress((void**)&gWM16, g_WM16);
    __half* gWqT = gW16;
    __half* gWkT = gW16 + 1 * 512 * 512;
    __half* gWvT = gW16 + 2 * 512 * 512;
    __half* gWo_ = gW16 + 3 * 512 * 512;
    __half* gWm  = gWM16;                  // Wm[i,k] = sum_j Wk[j,i] Wq[j,k]
    __half* gWn  = gWM16 + 512 * 512;      // Wn[j,i] = sum_k Wo[j,k] Wv[k,i]

    static cudaStream_t s2 = nullptr, s3 = nullptr;
    static cudaEvent_t evF = nullptr, evQ = nullptr, evH = nullptr;
    if (!s2) {
        cudaStreamCreateWithFlags(&s2, cudaStreamNonBlocking);
        cudaStreamCreateWithFlags(&s3, cudaStreamNonBlocking);
        cudaEventCreateWithFlags(&evF, cudaEventDisableTiming);
        cudaEventCreateWithFlags(&evQ, cudaEventDisableTiming);
        cudaEventCreateWithFlags(&evH, cudaEventDisableTiming);
        cudaFuncSetAttribute(mma_gemm_f16<false>,
                             cudaFuncAttributeMaxDynamicSharedMemorySize, GM_SMEM);
        cudaFuncSetAttribute(mma_gemm_f16<true>,
                             cudaFuncAttributeMaxDynamicSharedMemorySize, GM_SMEM);
        cudaFuncSetAttribute(tiny2_gemm_f16,
                             cudaFuncAttributeMaxDynamicSharedMemorySize, GM_SMEM);
        cudaFuncSetAttribute(attention_kernel,
                             cudaFuncAttributeMaxDynamicSharedMemorySize, AT_DYN);
    }

    int n8 = (MTOT * 512) / 8;

    // fork
    cudaEventRecord(evF, 0);
    cudaStreamWaitEvent(s2, evF, 0);
    cudaStreamWaitEvent(s3, evF, 0);
    cvt_f16_kernel<<<4096, 256, 0, s2>>>((const float4*)q, (uint4*)gq16, n8);
    cudaEventRecord(evQ, s2);
    cvt_f16_kernel<<<4096, 256, 0, s3>>>((const float4*)h, (uint4*)gh16, n8);
    cudaEventRecord(evH, s3);

    // main: weights -> folds
    prep_w_kernel<<<dim3(16, 16, 4), dim3(32, 8)>>>(Wq, Wk, Wv, Wo, gW16);
    tiny2_gemm_f16<<<dim3(4, 4, 2), 512, GM_SMEM>>>(gWkT, gWqT, gWm,
                                                    gWo_, gWvT, gWn);

    // join q -> qM
    cudaStreamWaitEvent(0, evQ, 0);
    mma_gemm_f16<false><<<dim3(4, MTOT / 128), 512, GM_SMEM>>>(
        gq16, gWm, nullptr, gQp, 512);

    // join h -> attention
    cudaStreamWaitEvent(0, evH, 0);
    attention_kernel<<<dim3(3, Bc), 256, AT_DYN>>>(gQp, gh16, mask, gX16);

    // out = X @ Wn^T + bias
    mma_gemm_f16<true><<<dim3(4, MTOT / 128), 512, GM_SMEM>>>(
        gX16, gWn, bo, out, 512);
}

// round 16
// speedup vs baseline: 1.0530x; 1.0139x over previous
#include <cuda_runtime.h>
#include <cuda_fp16.h>
#include <math.h>
#include <stdint.h>

// ---------------------------------------------------------------------------
// Problem constants
// ---------------------------------------------------------------------------
constexpr int Bc   = 512;
constexpr int Gc   = 131;
constexpr int MTOT = Bc * Gc;      // 67072
constexpr int LEAF_LO = 80;
constexpr int LEAF_HI = 130;

// Scratch (device globals: allocation-free)
__device__ __half g_q16[(size_t)MTOT * 512];    // q  (fp16)
__device__ __half g_h16[(size_t)MTOT * 512];    // h  (fp16)
__device__ __half g_Qp [(size_t)MTOT * 512];    // q' = q·M
__device__ __half g_X16[(size_t)MTOT * 512];    // X  = attn·h
__device__ __half g_W16[4][512 * 512];          // WqT, WkT, WvT, Wo (fp16)
__device__ __half g_WM16[2][512 * 512];         // Wm, Wn (folded, fp16)

// ---------------------------------------------------------------------------
// PTX helpers (baseline sm_75/80 PTX — valid for compute_103)
// ---------------------------------------------------------------------------
__device__ __forceinline__ uint32_t smem_u32(const void* p) {
    return (uint32_t)__cvta_generic_to_shared(p);
}
__device__ __forceinline__ void cp_async16(uint32_t sdst, const void* gsrc) {
    asm volatile("cp.async.cg.shared.global [%0], [%1], 16;" :: "r"(sdst), "l"(gsrc));
}
__device__ __forceinline__ void cp_async16z(uint32_t sdst, const void* gsrc, bool valid) {
    int sz = valid ? 16 : 0;
    asm volatile("cp.async.cg.shared.global [%0], [%1], 16, %2;"
                 :: "r"(sdst), "l"(gsrc), "r"(sz));
}
__device__ __forceinline__ void cp_commit() { asm volatile("cp.async.commit_group;"); }
__device__ __forceinline__ void cp_wait0()  { asm volatile("cp.async.wait_group 0;"); }
__device__ __forceinline__ void cp_wait1()  { asm volatile("cp.async.wait_group 1;"); }

__device__ __forceinline__ void ldsm_x4(uint32_t& r0, uint32_t& r1, uint32_t& r2,
                                        uint32_t& r3, uint32_t addr) {
    asm volatile("ldmatrix.sync.aligned.m8n8.x4.shared.b16 {%0,%1,%2,%3}, [%4];"
                 : "=r"(r0), "=r"(r1), "=r"(r2), "=r"(r3) : "r"(addr));
}
__device__ __forceinline__ void ldsm_x4_t(uint32_t& r0, uint32_t& r1, uint32_t& r2,
                                          uint32_t& r3, uint32_t addr) {
    asm volatile("ldmatrix.sync.aligned.m8n8.x4.trans.shared.b16 {%0,%1,%2,%3}, [%4];"
                 : "=r"(r0), "=r"(r1), "=r"(r2), "=r"(r3) : "r"(addr));
}
__device__ __forceinline__ void mma_f16(float* c, const uint32_t* a, const uint32_t* b) {
    asm volatile(
        "mma.sync.aligned.m16n8k16.row.col.f32.f16.f16.f32 "
        "{%0,%1,%2,%3}, {%4,%5,%6,%7}, {%8,%9}, {%0,%1,%2,%3};"
        : "+f"(c[0]), "+f"(c[1]), "+f"(c[2]), "+f"(c[3])
        : "r"(a[0]), "r"(a[1]), "r"(a[2]), "r"(a[3]), "r"(b[0]), "r"(b[1]));
}

// ---------------------------------------------------------------------------
// prep_all: z=0 cvt q->fp16, z=1 cvt h->fp16, z=2..4 transpose+cvt Wq/Wk/Wv,
// z=5 plain cvt Wo. One launch => all run concurrently.
// ---------------------------------------------------------------------------
__global__ void prep_all_kernel(const float4* __restrict__ q, const float4* __restrict__ h,
                                uint4* __restrict__ q16, uint4* __restrict__ h16,
                                const float* __restrict__ w0, const float* __restrict__ w1,
                                const float* __restrict__ w2, const float* __restrict__ w3,
                                __half* __restrict__ wout, int n8) {
    const int tx = threadIdx.x, ty = threadIdx.y;
    const int tid = ty * 32 + tx;
    const int z = blockIdx.z;
    if (z < 2) {
        const float4* in = z ? h : q;
        uint4* out = z ? h16 : q16;
        int blk = blockIdx.y * 16 + blockIdx.x;
        for (int i = blk * 256 + tid; i < n8; i += 256 * 256) {
            float4 v0 = in[2 * i], v1 = in[2 * i + 1];
            __half2 h0 = __floats2half2_rn(v0.x, v0.y);
            __half2 h1 = __floats2half2_rn(v0.z, v0.w);
            __half2 h2 = __floats2half2_rn(v1.x, v1.y);
            __half2 h3 = __floats2half2_rn(v1.z, v1.w);
            uint4 o;
            o.x = *reinterpret_cast<uint32_t*>(&h0);
            o.y = *reinterpret_cast<uint32_t*>(&h1);
            o.z = *reinterpret_cast<uint32_t*>(&h2);
            o.w = *reinterpret_cast<uint32_t*>(&h3);
            out[i] = o;
        }
    } else {
        __shared__ float tile[32][33];
        const int sel = z - 2;
        const float* in = (sel == 0) ? w0 : (sel == 1) ? w1 : (sel == 2) ? w2 : w3;
        __half* o = wout + (size_t)sel * 512 * 512;
        const int x = blockIdx.x * 32 + tx;
        const int y0 = blockIdx.y * 32;
        if (sel < 3) {
#pragma unroll
            for (int j = 0; j < 32; j += 8)
                tile[ty + j][tx] = in[(size_t)(y0 + ty + j) * 512 + x];
            __syncthreads();
            const int x2 = y0 + tx;
            const int y2 = blockIdx.x * 32;
#pragma unroll
            for (int j = 0; j < 32; j += 8)
                o[(size_t)(y2 + ty + j) * 512 + x2] = __float2half_rn(tile[tx][ty + j]);
        } else {
#pragma unroll
            for (int j = 0; j < 32; j += 8)
                o[(size_t)(y0 + ty + j) * 512 + x] =
                    __float2half_rn(in[(size_t)(y0 + ty + j) * 512 + x]);
        }
    }
}

// ---------------------------------------------------------------------------
// fp16 mma GEMM-NT, 512 threads (16 warps, 4m x 4n, warp tile 32x32):
// C[M,N] = A[M,512] @ W[N,512]^T. BM=BN=128, BK=64, 3-stage pipeline.
// ---------------------------------------------------------------------------
constexpr int GM_ROWH = 72;
constexpr int GM_STAGE_B = 256 * GM_ROWH * 2;     // 36864
constexpr int GM_STAGES = 3;
constexpr int GM_SMEM = GM_STAGES * GM_STAGE_B;   // 110592
constexpr int GM_ITERS = 8;

template <bool OUTF32>
__device__ __forceinline__ void gemm_body_f16(const __half* __restrict__ A,
                                              const __half* __restrict__ W,
                                              const float* __restrict__ bias,
                                              void* __restrict__ Cv, int CS,
                                              int bm, int bn) {
    extern __shared__ __align__(16) char smraw[];
    const uint32_t smb = smem_u32(smraw);
    const int tid = threadIdx.x;
    const int wid = tid >> 5;
    const int lane = tid & 31;
    const int wm = (wid & 3) * 32;
    const int wn = (wid >> 2) * 32;

    const __half* Ag = A + (size_t)bm * 512;
    const __half* Wg = W + (size_t)bn * 512;

    float c[2][4][4];
#pragma unroll
    for (int t = 0; t < 2; t++)
#pragma unroll
        for (int n = 0; n < 4; n++)
#pragma unroll
            for (int v = 0; v < 4; v++) c[t][n][v] = 0.f;

    const int lr = lane & 7;
    uint32_t aoff[2], boff[2];
#pragma unroll
    for (int t = 0; t < 2; t++)
        aoff[t] = (uint32_t)(((wm + t * 16 + ((lane >> 3) & 1) * 8 + lr) * GM_ROWH
                              + (lane >> 4) * 8) * 2);
#pragma unroll
    for (int jp = 0; jp < 2; jp++)
        boff[jp] = (uint32_t)(128 * GM_ROWH * 2
                              + ((wn + jp * 16 + ((lane >> 4) & 1) * 8 + lr) * GM_ROWH
                                 + ((lane >> 3) & 1) * 8) * 2);

    auto load_stage = [&](int s, int k0) {
        uint32_t base = smb + (uint32_t)(s * GM_STAGE_B);
#pragma unroll
        for (int i = 0; i < 2; i++) {
            int id = tid + i * 512;
            int row = id >> 3, c8 = (id & 7) << 3;
            cp_async16(base + (uint32_t)((row * GM_ROWH + c8) * 2),
                       Ag + (size_t)row * 512 + k0 + c8);
        }
#pragma unroll
        for (int i = 0; i < 2; i++) {
            int id = tid + i * 512;
            int row = id >> 3, c8 = (id & 7) << 3;
            cp_async16(base + (uint32_t)(((128 + row) * GM_ROWH + c8) * 2),
                       Wg + (size_t)row * 512 + k0 + c8);
        }
    };

    load_stage(0, 0);    cp_commit();
    load_stage(1, 64);   cp_commit();
    cp_wait1();
    __syncthreads();

    int sc = 0, sl = 2;
    for (int it = 0; it < GM_ITERS; ++it) {
        if (it + 2 < GM_ITERS) {
            load_stage(sl, (it + 2) * 64);
            cp_commit();
            sl = (sl == GM_STAGES - 1) ? 0 : sl + 1;
        }
        uint32_t base = smb + (uint32_t)(sc * GM_STAGE_B);
        sc = (sc == GM_STAGES - 1) ? 0 : sc + 1;
#pragma unroll
        for (int kk = 0; kk < 4; kk++) {
            uint32_t a[2][4], b[4][2];
#pragma unroll
            for (int t = 0; t < 2; t++)
                ldsm_x4(a[t][0], a[t][1], a[t][2], a[t][3], base + aoff[t] + kk * 32);
#pragma unroll
            for (int jp = 0; jp < 2; jp++) {
                uint32_t r0, r1, r2, r3;
                ldsm_x4(r0, r1, r2, r3, base + boff[jp] + kk * 32);
                b[2 * jp][0] = r0;     b[2 * jp][1] = r1;
                b[2 * jp + 1][0] = r2; b[2 * jp + 1][1] = r3;
            }
#pragma unroll
            for (int t = 0; t < 2; t++)
#pragma unroll
                for (int n = 0; n < 4; n++)
                    mma_f16(c[t][n], a[t], b[n]);
        }
        if (it + 2 < GM_ITERS)      cp_wait1();
        else if (it + 1 < GM_ITERS) cp_wait0();
        __syncthreads();
    }

    const int g = lane >> 2;
    const int q = lane & 3;
#pragma unroll
    for (int n = 0; n < 4; n++) {
        int col = bn + wn + n * 8 + 2 * q;
        float b0 = 0.f, b1 = 0.f;
        if (OUTF32) { b0 = bias[col]; b1 = bias[col + 1]; }
#pragma unroll
        for (int t = 0; t < 2; t++) {
            int row0 = bm + wm + t * 16 + g;
            if (OUTF32) {
                float* Cf = (float*)Cv;
                *reinterpret_cast<float2*>(Cf + (size_t)row0 * CS + col) =
                    make_float2(c[t][n][0] + b0, c[t][n][1] + b1);
                *reinterpret_cast<float2*>(Cf + (size_t)(row0 + 8) * CS + col) =
                    make_float2(c[t][n][2] + b0, c[t][n][3] + b1);
            } else {
                __half* Ch = (__half*)Cv;
                __half2 p0 = __floats2half2_rn(c[t][n][0], c[t][n][1]);
                __half2 p1 = __floats2half2_rn(c[t][n][2], c[t][n][3]);
                *reinterpret_cast<__half2*>(Ch + (size_t)row0 * CS + col) = p0;
                *reinterpret_cast<__half2*>(Ch + (size_t)(row0 + 8) * CS + col) = p1;
            }
        }
    }
}

template <bool OUTF32>
__global__ void __launch_bounds__(512, 2)
mma_gemm_f16(const __half* __restrict__ A, const __half* __restrict__ W,
             const float* __restrict__ bias, void* __restrict__ C, int CS) {
    gemm_body_f16<OUTF32>(A, W, bias, C, CS, blockIdx.y * 128, blockIdx.x * 128);
}

__global__ void __launch_bounds__(512, 2)
tiny2_gemm_f16(const __half* __restrict__ A0, const __half* __restrict__ W0,
               __half* __restrict__ C0,
               const __half* __restrict__ A1, const __half* __restrict__ W1,
               __half* __restrict__ C1) {
    if (blockIdx.z == 0)
        gemm_body_f16<false>(A0, W0, nullptr, C0, 512, blockIdx.y * 128, blockIdx.x * 128);
    else
        gemm_body_f16<false>(A1, W1, nullptr, C1, 512, blockIdx.y * 128, blockIdx.x * 128);
}

// ---------------------------------------------------------------------------
// FUSED attention. grid (3, Bc): x<2 -> 64-row mma tile; x==2 -> tail rows.
// Smem (dynamic, 97792 B):
//   [0, 39168):        phase1 stage0 -> phase3 V stage0
//   [39168, 78336):    phase1 stage1 -> fp32 stash Ss[64][132] -> V stage1
//   [78336, +19456):   Ps[64][152] fp16 probs
// V tile 0 is issued BEFORE softmax (stash no longer overlaps stage 0),
// so its load overlaps the softmax phase.
// ---------------------------------------------------------------------------
constexpr int SC_QB   = 64 * 72 * 2;              // 9216
constexpr int SC_STG  = SC_QB + 168 * 72 * 2;     // 33408
constexpr int HV_TILE = 144 * 136 * 2;            // 39168 whole V n-tile
constexpr int ST_OFF  = HV_TILE;                  // stash at 39168 (in stage-1 slot)
constexpr int ST_STR  = 132;                      // stash row stride (floats)
constexpr int PS_OFF  = 2 * HV_TILE;              // 78336
constexpr int PS_STR  = 152;
constexpr int AT_DYN  = PS_OFF + 64 * PS_STR * 2; // 97792

__global__ void __launch_bounds__(256)
attention_kernel(const __half* __restrict__ Q, const __half* __restrict__ Hm,
                 const int* __restrict__ mask, __half* __restrict__ X) {
    extern __shared__ __align__(16) char smc[];
    __shared__ int mask_s[144];
    const uint32_t smb = smem_u32(smc);
    const int tid = threadIdx.x;
    const int wid = tid >> 5;
    const int lane = tid & 31;
    const int b = blockIdx.y;

    // ======================= TAIL CTA (rows 128..130) =======================
    if (blockIdx.x == 2) {
        float* qs = reinterpret_cast<float*>(smc);           // [3][512]
        float* ps = reinterpret_cast<float*>(smc + 6144);    // [3][132]
        int*   mk = reinterpret_cast<int*>(smc + 7808);      // [132]
        const __half* Qb = Q  + ((size_t)b * Gc + 128) * 512;
        const __half* hb = Hm + (size_t)b * Gc * 512;

        for (int i = tid; i < 3 * 512; i += 256) qs[i] = __half2float(Qb[i]);
        if (tid < 132) mk[tid] = (tid < Gc) ? mask[b * Gc + tid] : 1;
        __syncthreads();

        for (int j = wid; j < Gc; j += 8) {
            const __half* hj = hb + (size_t)j * 512;
            float a0 = 0.f, a1 = 0.f, a2 = 0.f;
#pragma unroll
            for (int k = 0; k < 16; k++) {
                int idx = lane + k * 32;
                float hv = __half2float(hj[idx]);
                a0 = fmaf(hv, qs[idx], a0);
                a1 = fmaf(hv, qs[512 + idx], a1);
                a2 = fmaf(hv, qs[1024 + idx], a2);
            }
#pragma unroll
            for (int o = 16; o; o >>= 1) {
                a0 += __shfl_xor_sync(0xffffffffu, a0, o);
                a1 += __shfl_xor_sync(0xffffffffu, a1, o);
                a2 += __shfl_xor_sync(0xffffffffu, a2, o);
            }
            if (lane == 0) { ps[j] = a0; ps[132 + j] = a1; ps[264 + j] = a2; }
        }
        __syncthreads();

        if (wid < 3) {
            const int gi = 128 + wid;
            const bool li = (gi >= LEAF_LO) && (gi < LEAF_HI);
            const float norm = 0.04419417382415922f;
            float v[5];
            float mx = -3.0e38f;
#pragma unroll
            for (int ch = 0; ch < 5; ch++) {
                int j = lane + ch * 32;
                float val = -3.0e38f;
                if (j < Gc) {
                    bool mj = (mk[j] > 0) || (li && j >= LEAF_LO && j < LEAF_HI);
                    val = mj ? -30.f : ps[wid * 132 + j] * norm;
                }
                v[ch] = val;
                mx = fmaxf(mx, val);
            }
#pragma unroll
            for (int o = 16; o; o >>= 1) mx = fmaxf(mx, __shfl_xor_sync(0xffffffffu, mx, o));
            float e[5];
            float sum = 0.f;
#pragma unroll
            for (int ch = 0; ch < 5; ch++) {
                int j = lane + ch * 32;
                e[ch] = (j < Gc) ? expf(v[ch] - mx) : 0.f;
                sum += e[ch];
            }
#pragma unroll
            for (int o = 16; o; o >>= 1) sum += __shfl_xor_sync(0xffffffffu, sum, o);
            float inv = 1.f / sum;
#pragma unroll
            for (int ch = 0; ch < 5; ch++) {
                int j = lane + ch * 32;
                if (j < Gc) {
                    bool mj = (mk[j] > 0) || (li && j >= LEAF_LO && j < LEAF_HI);
                    ps[wid * 132 + j] = mj ? 0.f : e[ch] * inv;
                }
            }
        }
        __syncthreads();

        float acc[3][2] = {{0.f, 0.f}, {0.f, 0.f}, {0.f, 0.f}};
        for (int j = 0; j < Gc; j++) {
            float p0 = ps[j], p1 = ps[132 + j], p2 = ps[264 + j];
            float h0 = __half2float(hb[(size_t)j * 512 + tid]);
            float h1 = __half2float(hb[(size_t)j * 512 + tid + 256]);
            acc[0][0] = fmaf(p0, h0, acc[0][0]); acc[0][1] = fmaf(p0, h1, acc[0][1]);
            acc[1][0] = fmaf(p1, h0, acc[1][0]); acc[1][1] = fmaf(p1, h1, acc[1][1]);
            acc[2][0] = fmaf(p2, h0, acc[2][0]); acc[2][1] = fmaf(p2, h1, acc[2][1]);
        }
        __half* Xb = X + ((size_t)b * Gc + 128) * 512;
#pragma unroll
        for (int i = 0; i < 3; i++) {
            Xb[(size_t)i * 512 + tid]       = __float2half_rn(acc[i][0]);
            Xb[(size_t)i * 512 + tid + 256] = __float2half_rn(acc[i][1]);
        }
        return;
    }

    // ======================= MAIN CTA (64 rows) =============================
    const int m0 = blockIdx.x * 64;
    if (tid < 144) mask_s[tid] = (tid < Gc) ? mask[b * Gc + tid] : 1;

    const __half* Qb = Q  + (size_t)b * Gc * 512;
    const __half* Kb = Hm + (size_t)b * Gc * 512;   // K and V are both h

    // whole-tile V loader (usable once its target region is free)
    auto vload_tile = [&](int s, int n0) {
        uint32_t vbse = smb + (uint32_t)(s * HV_TILE);
#pragma unroll
        for (int i = 0; i < 9; i++) {
            int id = tid + i * 256;
            int row = id >> 4, c8 = (id & 15) << 3;
            bool v = row < Gc;
            const __half* src = v ? Kb + (size_t)row * 512 + n0 + c8 : Kb;
            cp_async16z(vbse + (uint32_t)((row * 136 + c8) * 2), src, v);
        }
    };

    // ---- phase 1: scores (fp16 mma), 2-stage pipeline, K=512 = 8 x 64 ----
    {
        const int wm = (wid & 1) * 32;
        const int wn = (wid >> 1) * 40;
        const int lr = lane & 7;

        float c[2][5][4];
#pragma unroll
        for (int t = 0; t < 2; t++)
#pragma unroll
            for (int n = 0; n < 5; n++)
#pragma unroll
                for (int v = 0; v < 4; v++) c[t][n][v] = 0.f;

        uint32_t aoff[2], boff[3];
#pragma unroll
        for (int t = 0; t < 2; t++)
            aoff[t] = (uint32_t)(((wm + t * 16 + ((lane >> 3) & 1) * 8 + lr) * 72
                                  + (lane >> 4) * 8) * 2);
#pragma unroll
        for (int jp = 0; jp < 3; jp++)
            boff[jp] = (uint32_t)(SC_QB
                                  + ((wn + jp * 16 + ((lane >> 4) & 1) * 8 + lr) * 72
                                     + ((lane >> 3) & 1) * 8) * 2);

        auto load_stage = [&](int s, int k0) {
            uint32_t qb = smb + (uint32_t)(s * SC_STG);
            uint32_t kb = qb + SC_QB;
#pragma unroll
            for (int l = 0; l < 2; l++) {
                int id = tid + l * 256;
                int row = id >> 3, c8 = (id & 7) << 3;
                cp_async16(qb + (uint32_t)((row * 72 + c8) * 2),
                           Qb + (size_t)(m0 + row) * 512 + k0 + c8);
            }
#pragma unroll
            for (int i = 0; i < 5; i++) {
                int id = tid + i * 256;
                int row = id >> 3, c8 = (id & 7) << 3;
                bool v = row < Gc;
                const __half* src = v ? Kb + (size_t)row * 512 + k0 + c8 : Kb;
                cp_async16z(kb + (uint32_t)((row * 72 + c8) * 2), src, v);
            }
        };

        load_stage(0, 0);
        cp_commit();
        cp_wait0();
        __syncthreads();

        for (int it = 0; it < 8; ++it) {
            if (it + 1 < 8) {
                load_stage((it + 1) & 1, (it + 1) * 64);
                cp_commit();
            }
            uint32_t qb = smb + (uint32_t)((it & 1) * SC_STG);
#pragma unroll
            for (int kk = 0; kk < 4; kk++) {
                uint32_t a[2][4], bfr[6][2];
#pragma unroll
                for (int t = 0; t < 2; t++)
                    ldsm_x4(a[t][0], a[t][1], a[t][2], a[t][3], qb + aoff[t] + kk * 32);
#pragma unroll
                for (int jp = 0; jp < 3; jp++) {
                    uint32_t r0, r1, r2, r3;
                    ldsm_x4(r0, r1, r2, r3, qb + boff[jp] + kk * 32);
                    bfr[2 * jp][0] = r0;     bfr[2 * jp][1] = r1;
                    bfr[2 * jp + 1][0] = r2; bfr[2 * jp + 1][1] = r3;
                }
#pragma unroll
                for (int t = 0; t < 2; t++)
#pragma unroll
                    for (int n = 0; n < 5; n++)
                        mma_f16(c[t][n], a[t], bfr[n]);
            }
            if (it + 1 < 8) cp_wait0();
            __syncthreads();
        }

        // stash accumulators fp32 into stage-1 slot: Ss[64][132], cols < 131 only
        float* Ss = reinterpret_cast<float*>(smc + ST_OFF);
        const int g = lane >> 2;
        const int qd = lane & 3;
#pragma unroll
        for (int t = 0; t < 2; t++) {
            int r0 = wm + t * 16 + g;
#pragma unroll
            for (int n = 0; n < 5; n++) {
                int col = wn + n * 8 + 2 * qd;
                if (col < 131) {   // cols >= 131 are masked before softmax reads
                    *reinterpret_cast<float2*>(&Ss[r0 * ST_STR + col]) =
                        make_float2(c[t][n][0], c[t][n][1]);
                    *reinterpret_cast<float2*>(&Ss[(r0 + 8) * ST_STR + col]) =
                        make_float2(c[t][n][2], c[t][n][3]);
                }
            }
        }
    }
    __syncthreads();

    // V tile 0 loads into [0, HV_TILE) — disjoint from the stash — while
    // softmax runs below.
    vload_tile(0, 0);
    cp_commit();

    // ---- phase 2: softmax -> Ps[64][152] fp16 ----
    {
        float* Ss = reinterpret_cast<float*>(smc + ST_OFF);
        __half* Ps = reinterpret_cast<__half*>(smc + PS_OFF);
        const float norm = 0.04419417382415922f;
#pragma unroll
        for (int rr = 0; rr < 8; rr++) {
            int i_loc = wid * 8 + rr;
            int gi = m0 + i_loc;                    // < 128
            bool li = (gi >= LEAF_LO) && (gi < LEAF_HI);
            float v[5];
            float mx = -3.0e38f;
#pragma unroll
            for (int ch = 0; ch < 5; ch++) {
                int j = lane + ch * 32;
                float val = -3.0e38f;
                if (j < Gc) {
                    float s = Ss[i_loc * ST_STR + j] * norm;
                    bool mj = (mask_s[j] > 0) || (li && j >= LEAF_LO && j < LEAF_HI);
                    val = mj ? -30.f : s;
                }
                v[ch] = val;
                mx = fmaxf(mx, val);
            }
#pragma unroll
            for (int o = 16; o; o >>= 1) mx = fmaxf(mx, __shfl_xor_sync(0xffffffffu, mx, o));
            float e[5];
            float sum = 0.f;
#pragma unroll
            for (int ch = 0; ch < 5; ch++) {
                int j = lane + ch * 32;
                e[ch] = (j < Gc) ? expf(v[ch] - mx) : 0.f;
                sum += e[ch];
            }
#pragma unroll
            for (int o = 16; o; o >>= 1) sum += __shfl_xor_sync(0xffffffffu, sum, o);
            float inv = 1.f / sum;
#pragma unroll
            for (int ch = 0; ch < 5; ch++) {
                int j = lane + ch * 32;
                if (j < 144) {
                    float p = 0.f;
                    if (j < Gc) {
                        bool mj = (mask_s[j] > 0) || (li && j >= LEAF_LO && j < LEAF_HI);
                        p = mj ? 0.f : e[ch] * inv;
                    }
                    Ps[i_loc * PS_STR + j] = __float2half_rn(p);
                }
            }
        }
    }
    __syncthreads();

    // ---- phase 3: heads. Whole-tile V double buffering (tile 0 in flight) ----
    {
        const int wm = (wid & 1) * 32;
        const int wn = (wid >> 1) * 32;
        const int lr = lane & 7;
        const uint32_t ps_base = smb + PS_OFF;

        uint32_t aoff[2];
#pragma unroll
        for (int t = 0; t < 2; t++)
            aoff[t] = (uint32_t)(((wm + t * 16 + ((lane >> 3) & 1) * 8 + lr) * PS_STR
                                  + (lane >> 4) * 8) * 2);
        const int tk = lr + ((lane >> 3) & 1) * 8;
        const int tn = (lane >> 4) * 8;

        for (int nt = 0; nt < 4; nt++) {
            cp_wait0();
            __syncthreads();
            if (nt + 1 < 4) {
                vload_tile((nt + 1) & 1, (nt + 1) * 128);
                cp_commit();
            }
            uint32_t vbse = smb + (uint32_t)((nt & 1) * HV_TILE);
            const int n0 = nt * 128;

            float c[2][4][4];
#pragma unroll
            for (int t = 0; t < 2; t++)
#pragma unroll
                for (int n = 0; n < 4; n++)
#pragma unroll
                    for (int v = 0; v < 4; v++) c[t][n][v] = 0.f;

#pragma unroll
            for (int it = 0; it < 9; ++it) {
                uint32_t a[2][4], bfr[4][2];
#pragma unroll
                for (int t = 0; t < 2; t++)
                    ldsm_x4(a[t][0], a[t][1], a[t][2], a[t][3],
                            ps_base + aoff[t] + it * 32);
#pragma unroll
                for (int p = 0; p < 2; p++) {
                    uint32_t r0, r1, r2, r3;
                    ldsm_x4_t(r0, r1, r2, r3,
                              vbse + (uint32_t)(((it * 16 + tk) * 136
                                                 + wn + p * 16 + tn) * 2));
                    bfr[2 * p][0] = r0;     bfr[2 * p][1] = r1;
                    bfr[2 * p + 1][0] = r2; bfr[2 * p + 1][1] = r3;
                }
#pragma unroll
                for (int t = 0; t < 2; t++)
#pragma unroll
                    for (int n = 0; n < 4; n++)
                        mma_f16(c[t][n], a[t], bfr[n]);
            }

            const int g = lane >> 2;
            const int qd = lane & 3;
#pragma unroll
            for (int t = 0; t < 2; t++) {
#pragma unroll
                for (int n = 0; n < 4; n++) {
                    int col = n0 + wn + n * 8 + 2 * qd;
                    int i0r = m0 + wm + t * 16 + g;
                    __half2 p0 = __floats2half2_rn(c[t][n][0], c[t][n][1]);
                    __half2 p1 = __floats2half2_rn(c[t][n][2], c[t][n][3]);
                    *reinterpret_cast<__half2*>(X + ((size_t)b * Gc + i0r) * 512 + col) = p0;
                    *reinterpret_cast<__half2*>(X + ((size_t)b * Gc + i0r + 8) * 512 + col) = p1;
                }
            }
        }
    }
}

// ---------------------------------------------------------------------------
// Launch (r13 structure: single stream, one concurrent prep launch)
// ---------------------------------------------------------------------------
extern "C" void kernel_launch(void* const* d_in, const int* in_sizes, int n_in,
                              void* d_out, int out_size) {
    const float* q    = (const float*)d_in[0];
    const int*   mask = (const int*)d_in[1];
    const float* h    = (const float*)d_in[4];
    const float* Wq   = (const float*)d_in[5];
    const float* Wk   = (const float*)d_in[6];
    const float* Wv   = (const float*)d_in[7];
    const float* Wo   = (const float*)d_in[8];
    const float* bo   = (const float*)d_in[9];
    float* out = (float*)d_out;

    __half *gq16, *gh16, *gQp, *gX16, *gW16, *gWM16;
    cudaGetSymbolAddress((void**)&gq16, g_q16);
    cudaGetSymbolAddress((void**)&gh16, g_h16);
    cudaGetSymbolAddress((void**)&gQp,  g_Qp);
    cudaGetSymbolAddress((void**)&gX16, g_X16);
    cudaGetSymbolAddress((void**)&gW16, g_W16);
    cudaGetSymbolAddress((void**)&gWM16, g_WM16);
    __half* gWqT = gW16;
    __half* gWkT = gW16 + 1 * 512 * 512;
    __half* gWvT = gW16 + 2 * 512 * 512;
    __half* gWo_ = gW16 + 3 * 512 * 512;
    __half* gWm  = gWM16;                  // Wm[i,k] = sum_j Wk[j,i] Wq[j,k]
    __half* gWn  = gWM16 + 512 * 512;      // Wn[j,i] = sum_k Wo[j,k] Wv[k,i]

    cudaFuncSetAttribute(mma_gemm_f16<false>,
                         cudaFuncAttributeMaxDynamicSharedMemorySize, GM_SMEM);
    cudaFuncSetAttribute(mma_gemm_f16<true>,
                         cudaFuncAttributeMaxDynamicSharedMemorySize, GM_SMEM);
    cudaFuncSetAttribute(tiny2_gemm_f16,
                         cudaFuncAttributeMaxDynamicSharedMemorySize, GM_SMEM);
    cudaFuncSetAttribute(attention_kernel,
                         cudaFuncAttributeMaxDynamicSharedMemorySize, AT_DYN);

    int n8 = (MTOT * 512) / 8;

    // 1) all prep work in one concurrent launch
    prep_all_kernel<<<dim3(16, 16, 6), dim3(32, 8)>>>(
        (const float4*)q, (const float4*)h, (uint4*)gq16, (uint4*)gh16,
        Wq, Wk, Wv, Wo, gW16, n8);

    // 2) fold both weight products
    tiny2_gemm_f16<<<dim3(4, 4, 2), 512, GM_SMEM>>>(gWkT, gWqT, gWm,
                                                    gWo_, gWvT, gWn);

    // 3) q' = q @ Wm^T
    mma_gemm_f16<false><<<dim3(4, MTOT / 128), 512, GM_SMEM>>>(
        gq16, gWm, nullptr, gQp, 512);

    // 4) fused attention (V tile 0 overlapped with softmax)
    attention_kernel<<<dim3(3, Bc), 256, AT_DYN>>>(gQp, gh16, mask, gX16);

    // 5) out = X @ Wn^T + bias
    mma_gemm_f16<true><<<dim3(4, MTOT / 128), 512, GM_SMEM>>>(
        gX16, gWn, bo, out, 512);
}